// round 16
// baseline (speedup 1.0000x reference)
#include <cuda_runtime.h>
#include <cstdint>

#define BATCH     8
#define NPTS      32768
#define CIN_DIM   128
#define MS        (NPTS / 4)          // 8192 samples
#define CPB       16                  // CTAs per batch (no clusters!)
#define NTHREADS  256
#define NWARPS    (NTHREADS / 32)     // 8
#define PPT       (NPTS / (CPB * NTHREADS))   // 8 points per thread
#define NSLOTS    (CPB * NWARPS)              // 128 producer slots per batch

typedef unsigned long long ull;

// scratch (device globals: no allocation allowed)
__device__ int   g_sample_idx[BATCH * MS];
__device__ ull   g_key[BATCH][2][NSLOTS];   // {vbits<<32 | g<<17 | tag}
__device__ uint4 g_crd[BATCH][2][NSLOTS];   // winner coords x,y,z

__global__ void __launch_bounds__(NTHREADS, 1)
fps_kernel(const float* __restrict__ xyz)
{
    const int cta   = blockIdx.x & (CPB - 1);
    const int batch = blockIdx.x / CPB;
    const int tid   = threadIdx.x;
    const int warp  = tid >> 5;
    const int lane  = tid & 31;

    const float* sx = xyz + (size_t)batch * 3 * NPTS;
    const float* sy = sx + NPTS;
    const float* sz = sy + NPTS;

    const int base = cta * (NTHREADS * PPT) + tid;   // g = base + k*NTHREADS

    float px[PPT], py[PPT], pz[PPT], dst[PPT];
#pragma unroll
    for (int k = 0; k < PPT; k++) {
        const int g = base + k * NTHREADS;
        px[k]  = sx[g];
        py[k]  = sy[g];
        pz[k]  = sz[g];
        dst[k] = 1e10f;
    }

    // initial farthest = point 0 (reference's deterministic seed)
    float cx = sx[0], cy = sy[0], cz = sz[0];
    int   fi = 0;

    const int myslot = cta * NWARPS + warp;
    ull* const   myk0 = &g_key[batch][0][myslot];
    ull* const   myk1 = &g_key[batch][1][myslot];
    uint4* const myc0 = &g_crd[batch][0][myslot];
    uint4* const myc1 = &g_crd[batch][1][myslot];

    for (int t = 0; t < MS; t++) {
        if (cta == 0 && tid == 0)
            g_sample_idx[batch * MS + t] = fi;
        if (t == MS - 1) break;                 // last fi already recorded

        // ---- distance update + per-thread argmax (first-max keeps lowest g) ----
        float bv, bx, by, bz;
        uint32_t bg;
        {
            const float dx = __fadd_rn(px[0], -cx);
            const float dy = __fadd_rn(py[0], -cy);
            const float dz = __fadd_rn(pz[0], -cz);
            const float d  = __fmaf_rn(dz, dz, __fmaf_rn(dx, dx, __fmul_rn(dy, dy)));
            const float nd = fminf(dst[0], d);
            dst[0] = nd;
            bv = nd; bg = (uint32_t)base; bx = px[0]; by = py[0]; bz = pz[0];
        }
#pragma unroll
        for (int k = 1; k < PPT; k++) {
            const float dx = __fadd_rn(px[k], -cx);
            const float dy = __fadd_rn(py[k], -cy);
            const float dz = __fadd_rn(pz[k], -cz);
            const float d  = __fmaf_rn(dz, dz, __fmaf_rn(dx, dx, __fmul_rn(dy, dy)));
            const float nd = fminf(dst[k], d);
            dst[k] = nd;
            const bool p = nd > bv;             // strict > keeps earliest (lowest g)
            bv = p ? nd : bv;
            bg = p ? (uint32_t)(base + k * NTHREADS) : bg;
            bx = p ? px[k] : bx;
            by = p ? py[k] : by;
            bz = p ? pz[k] : bz;
        }

        // ---- warp argmax via redux (value max, then min index among maxima) ----
        const uint32_t vb   = __float_as_uint(bv);          // >=0 -> u32-ordered
        const uint32_t wmax = __reduce_max_sync(0xffffffffu, vb);
        const bool     eq   = (vb == wmax);
        const uint32_t gmin = __reduce_min_sync(0xffffffffu, eq ? bg : 0xffffffffu);
        const bool     win  = eq && (bg == gmin);           // unique lane

        const int par = t & 1;
        const uint32_t tag = (uint32_t)(t + 1);             // 1..8191 (17-bit field)

        // ---- push: winning lane writes coords (weak) then key (release) ----
        if (win) {
            uint4* mc = par ? myc1 : myc0;
            ull*   mk = par ? myk1 : myk0;
            asm volatile("st.global.v4.b32 [%0], {%1,%2,%3,%4};"
                         :: "l"(mc), "r"(__float_as_uint(bx)), "r"(__float_as_uint(by)),
                            "r"(__float_as_uint(bz)), "r"(0u) : "memory");
            const ull key = ((ull)wmax << 32) | ((ull)gmin << 17) | (ull)tag;
            asm volatile("st.release.gpu.global.b64 [%0], %1;"
                         :: "l"(mk), "l"(key) : "memory");
        }

        // ---- consume: each lane acquire-polls 4 slots (lane + 32j) ----
        ull* const kbase = &g_key[batch][par][0];
        ull kv[4];
        {
            uint32_t done = 0;
            while (done != 0xFu) {
#pragma unroll
                for (int j = 0; j < 4; j++) {
                    if (!(done & (1u << j))) {
                        ull v;
                        asm volatile("ld.acquire.gpu.global.b64 %0, [%1];"
                                     : "=l"(v) : "l"(kbase + lane + 32 * j) : "memory");
                        if (((uint32_t)v & 0x1FFFFu) == tag) { kv[j] = v; done |= 1u << j; }
                    }
                }
            }
        }

        // local best of 4 (value desc, index asc)
        uint32_t vm = (uint32_t)(kv[0] >> 32);
        uint32_t gm = ((uint32_t)kv[0] >> 17) & 0x7FFFu;
        int      sj = 0;
#pragma unroll
        for (int j = 1; j < 4; j++) {
            const uint32_t v = (uint32_t)(kv[j] >> 32);
            const uint32_t g = ((uint32_t)kv[j] >> 17) & 0x7FFFu;
            const bool b = (v > vm) || (v == vm && g < gm);
            vm = b ? v : vm; gm = b ? g : gm; sj = b ? j : sj;
        }

        // prefetch coords of local-best slot (overlaps the redux below)
        uint32_t lx, ly, lz, lw;
        asm volatile("ld.global.v4.b32 {%0,%1,%2,%3}, [%4];"
                     : "=r"(lx), "=r"(ly), "=r"(lz), "=r"(lw)
                     : "l"(&g_crd[batch][par][lane + 32 * sj]) : "memory");

        const uint32_t cmax = __reduce_max_sync(0xffffffffu, vm);
        const uint32_t cfi  = __reduce_min_sync(0xffffffffu, (vm == cmax) ? gm : 0xffffffffu);

        // winner slot -> owning lane; its local best IS the winner
        // g = cta*2048 + k*256 + tid : cta = g>>11, warp = (g&255)>>5
        const int wslot = ((int)(cfi >> 11) << 3) | (((int)cfi & 255) >> 5);
        const int wlane = wslot & 31;
        cx = __uint_as_float(__shfl_sync(0xffffffffu, lx, wlane));
        cy = __uint_as_float(__shfl_sync(0xffffffffu, ly, wlane));
        cz = __uint_as_float(__shfl_sync(0xffffffffu, lz, wlane));
        fi = (int)cfi;
    }
}

// Gather epilogue: out = [xyz_sampled (B,3,M) | feature_sampled (B,CIN,M)]
__global__ void gather_kernel(const float* __restrict__ xyz,
                              const float* __restrict__ feat,
                              float* __restrict__ out)
{
    const int m = blockIdx.x * blockDim.x + threadIdx.x;   // 0..MS-1
    const int b = blockIdx.y;
    if (m >= MS) return;

    const int i = g_sample_idx[b * MS + m];

    const float* sxyz = xyz + (size_t)b * 3 * NPTS;
    float*       oxyz = out + (size_t)b * 3 * MS;
#pragma unroll
    for (int c = 0; c < 3; c++)
        oxyz[(size_t)c * MS + m] = sxyz[(size_t)c * NPTS + i];

    const float* sf = feat + (size_t)b * CIN_DIM * NPTS;
    float*       of = out + (size_t)BATCH * 3 * MS + (size_t)b * CIN_DIM * MS;
#pragma unroll 8
    for (int c = 0; c < CIN_DIM; c++)
        of[(size_t)c * MS + m] = sf[(size_t)c * NPTS + i];
}

extern "C" void kernel_launch(void* const* d_in, const int* in_sizes, int n_in,
                              void* d_out, int out_size)
{
    const float* xyz  = (const float*)d_in[0];   // [B,3,N] fp32
    const float* feat = (const float*)d_in[1];   // [B,CIN,N] fp32
    float*       out  = (float*)d_out;

    fps_kernel<<<BATCH * CPB, NTHREADS>>>(xyz);

    dim3 grid((MS + 255) / 256, BATCH);
    gather_kernel<<<grid, 256>>>(xyz, feat, out);
}